// round 5
// baseline (speedup 1.0000x reference)
#include <cuda_runtime.h>
#include <math.h>

#define D 128
#define WIN 128
#define BATCH 8
#define SEQ 8192
#define STR 132                        // smem row stride in floats (k-major rows)
#define GB_OFF (3 * 128 * STR)         // gelu(beta) table after 3 buffers
#define SMEM_BYTES ((3 * 128 * STR + 128) * 4)
#define SCALE 0.08838834764831845f     // 1/sqrt(128)

typedef unsigned long long ull;

// Fused weights, row-major [d][j]:  g_M = (Wq Wk^T)*SCALE,  g_N = Wv Wo
__device__ float g_M[D * D];
__device__ float g_N[D * D];

// ---------------- f32x2 helpers ----------------
__device__ __forceinline__ ull pk(float x, float y) {
    ull r;
    asm("mov.b64 %0, {%1, %2};" : "=l"(r) : "f"(x), "f"(y));
    return r;
}
__device__ __forceinline__ void upk(ull v, float& x, float& y) {
    asm("mov.b64 {%0, %1}, %2;" : "=f"(x), "=f"(y) : "l"(v));
}
__device__ __forceinline__ void fma2(ull& d, ull a, ull b) {
    asm("fma.rn.f32x2 %0, %1, %2, %0;" : "+l"(d) : "l"(a), "l"(b));
}
__device__ __forceinline__ float rmax16(float v) {
    #pragma unroll
    for (int off = 8; off; off >>= 1)
        v = fmaxf(v, __shfl_xor_sync(0xffffffffu, v, off, 16));
    return v;
}
__device__ __forceinline__ float rsum16(float v) {
    #pragma unroll
    for (int off = 8; off; off >>= 1)
        v += __shfl_xor_sync(0xffffffffu, v, off, 16);
    return v;
}
__device__ __forceinline__ float gelu(float y) {
    return 0.5f * y * (1.f + erff(y * 0.70710678118654752f));
}

// ---------------------------------------------------------------------------
// Precompute fused weights. grid=256: blocks 0..127 -> M row d, 128..255 -> N.
//   g_M[d][t] = SCALE * sum_f Wq[d][f] * Wk[t][f]
//   g_N[d][t] =         sum_f Wv[d][f] * Wo[f][t]
// 4 independent accumulator chains for ILP.
// ---------------------------------------------------------------------------
__global__ void __launch_bounds__(128, 8)
precompute_kernel(const float* __restrict__ Wq, const float* __restrict__ Wk,
                  const float* __restrict__ Wv, const float* __restrict__ Wo) {
    __shared__ float w[D];
    int t = threadIdx.x;
    if (blockIdx.x < 128) {
        int d = blockIdx.x;
        w[t] = Wq[d * D + t];
        __syncthreads();
        const float4* row = (const float4*)(Wk + t * D);
        float a0 = 0.f, a1 = 0.f, a2 = 0.f, a3 = 0.f;
        #pragma unroll
        for (int f4 = 0; f4 < 32; f4 += 4) {
            float4 k0 = __ldg(&row[f4 + 0]);
            float4 k1 = __ldg(&row[f4 + 1]);
            float4 k2 = __ldg(&row[f4 + 2]);
            float4 k3 = __ldg(&row[f4 + 3]);
            a0 += w[f4*4+0]*k0.x + w[f4*4+1]*k0.y + w[f4*4+2]*k0.z + w[f4*4+3]*k0.w;
            a1 += w[f4*4+4]*k1.x + w[f4*4+5]*k1.y + w[f4*4+6]*k1.z + w[f4*4+7]*k1.w;
            a2 += w[f4*4+8]*k2.x + w[f4*4+9]*k2.y + w[f4*4+10]*k2.z + w[f4*4+11]*k2.w;
            a3 += w[f4*4+12]*k3.x + w[f4*4+13]*k3.y + w[f4*4+14]*k3.z + w[f4*4+15]*k3.w;
        }
        g_M[d * D + t] = (a0 + a1 + a2 + a3) * SCALE;
    } else {
        int d = blockIdx.x - 128;
        w[t] = Wv[d * D + t];
        __syncthreads();
        float a0 = 0.f, a1 = 0.f, a2 = 0.f, a3 = 0.f;
        #pragma unroll 8
        for (int f = 0; f < D; f += 4) {
            a0 += w[f + 0] * __ldg(&Wo[(f + 0) * D + t]);
            a1 += w[f + 1] * __ldg(&Wo[(f + 1) * D + t]);
            a2 += w[f + 2] * __ldg(&Wo[(f + 2) * D + t]);
            a3 += w[f + 3] * __ldg(&Wo[(f + 3) * D + t]);
        }
        g_N[d * D + t] = a0 + a1 + a2 + a3;
    }
}

// ---------------------------------------------------------------------------
// 4x8 register-tile GEMM over k-major operands (stride STR):
//   acc[r][p] covers (i0+r, j0+2p / j0+2p+1):
//   acc += A[k][i0+r] * (B[k][j0+2p], B[k][j0+2p+1])
// ---------------------------------------------------------------------------
__device__ __forceinline__ void gemm4x8(const float* __restrict__ A,
                                        const float* __restrict__ B,
                                        int i0, int j0, ull acc[16]) {
    #pragma unroll
    for (int q = 0; q < 16; q++) acc[q] = 0ull;

    #pragma unroll 2
    for (int k = 0; k < D; k++) {
        const float* ar = A + k * STR + i0;
        const float* br = B + k * STR + j0;
        float4 a = *(const float4*)ar;
        float4 b0 = *(const float4*)br;
        float4 b1 = *(const float4*)(br + 4);
        ull bp0 = pk(b0.x, b0.y), bp1 = pk(b0.z, b0.w);
        ull bp2 = pk(b1.x, b1.y), bp3 = pk(b1.z, b1.w);
        float av[4] = {a.x, a.y, a.z, a.w};
        #pragma unroll
        for (int r = 0; r < 4; r++) {
            ull ad = pk(av[r], av[r]);
            fma2(acc[r * 4 + 0], ad, bp0);
            fma2(acc[r * 4 + 1], ad, bp1);
            fma2(acc[r * 4 + 2], ad, bp2);
            fma2(acc[r * 4 + 3], ad, bp3);
        }
    }
}

// ---------------------------------------------------------------------------
// Main fused kernel: one CTA per (batch, 128-token block). 512 threads.
// Thread (tx = tid&15, ty = tid>>4 in 0..31) owns rows i0=ty*4, cols j0=tx*8.
// Buffers (k-major [k][row], stride STR):
//   sX = X^T[d][i]      sW = M[d][j] -> T^T[j][i] -> P^T[u][i]
//   sV = N[d][j] -> U[u][d]
// Also writes the constant (zero-padded-input) half block: gelu(beta).
// ---------------------------------------------------------------------------
__global__ void __launch_bounds__(512, 1)
attn_kernel(const float* __restrict__ x, const float* __restrict__ gamma,
            const float* __restrict__ beta, float* __restrict__ out) {
    extern __shared__ float sm[];
    float* sX = sm;
    float* sW = sm + 128 * STR;
    float* sV = sm + 2 * 128 * STR;
    float* sGB = sm + GB_OFF;

    const int tid = threadIdx.x;
    const int tx = tid & 15, ty = tid >> 4;
    const int i0 = ty * 4, j0 = tx * 8;
    const int blk = blockIdx.x;
    const int b = blk >> 6, n = blk & 63;

    // ---- stage X^T, M, N; compute gelu(beta) table ----
    {
        const float4* Xg4 = (const float4*)(x + (b * SEQ + n * WIN) * D);
        const float4* M4 = (const float4*)g_M;
        const float4* N4 = (const float4*)g_N;
        #pragma unroll 4
        for (int i = tid; i < 4096; i += 512) {
            int r = i >> 5;            // row (token for X, k for W)
            int c4 = (i & 31) * 4;     // feature base
            float4 v = Xg4[i];
            sX[(c4 + 0) * STR + r] = v.x;
            sX[(c4 + 1) * STR + r] = v.y;
            sX[(c4 + 2) * STR + r] = v.z;
            sX[(c4 + 3) * STR + r] = v.w;
            *(float4*)&sW[r * STR + c4] = M4[i];
            *(float4*)&sV[r * STR + c4] = N4[i];
        }
        if (tid < 128) sGB[tid] = gelu(beta[tid]);
    }
    __syncthreads();

    // ---- constant half block: out[b][S + n*WIN .. +128] = gelu(beta) ----
    {
        float4* dst = (float4*)(out + ((size_t)b * 2 * SEQ + SEQ + n * WIN) * D);
        int row = tid >> 2;            // 0..127
        int cb = (tid & 3) * 32;       // col base
        #pragma unroll
        for (int q = 0; q < 8; q++) {
            int c = cb + q * 4;
            float4 v = make_float4(sGB[c], sGB[c + 1], sGB[c + 2], sGB[c + 3]);
            dst[row * 32 + (c >> 2)] = v;
        }
    }

    ull acc[16];

    // ---- G1: T^T[j][i] = sum_d M[d][j] * X^T[d][i]  (scale folded in M) ----
    gemm4x8(sW, sX, i0, j0, acc);      // rows = j, cols = i
    __syncthreads();                   // all G1 reads of sW done
    #pragma unroll
    for (int r = 0; r < 4; r++) {
        float v0, v1, v2, v3, v4, v5, v6, v7;
        upk(acc[r * 4 + 0], v0, v1);
        upk(acc[r * 4 + 1], v2, v3);
        upk(acc[r * 4 + 2], v4, v5);
        upk(acc[r * 4 + 3], v6, v7);
        *(float4*)&sW[(i0 + r) * STR + j0] = make_float4(v0, v1, v2, v3);
        *(float4*)&sW[(i0 + r) * STR + j0 + 4] = make_float4(v4, v5, v6, v7);
    }
    __syncthreads();

    // ---- G2: S[i][u] = sum_f T^T[f][i] * X^T[f][u] ----
    gemm4x8(sW, sX, i0, j0, acc);      // rows = i, cols = u

    // ---- softmax over u (across 16 tx lanes) ----
    float p[4][8];
    #pragma unroll
    for (int r = 0; r < 4; r++) {
        float v[8];
        upk(acc[r * 4 + 0], v[0], v[1]);
        upk(acc[r * 4 + 1], v[2], v[3]);
        upk(acc[r * 4 + 2], v[4], v[5]);
        upk(acc[r * 4 + 3], v[6], v[7]);
        float m = v[0];
        #pragma unroll
        for (int c = 1; c < 8; c++) m = fmaxf(m, v[c]);
        m = rmax16(m);
        float s = 0.f;
        #pragma unroll
        for (int c = 0; c < 8; c++) {
            v[c] = __expf(v[c] - m);
            s += v[c];
        }
        s = rsum16(s);
        float inv = 1.0f / s;
        #pragma unroll
        for (int c = 0; c < 8; c++) p[r][c] = v[c] * inv;
    }
    __syncthreads();                   // all G2 reads of sW done

    // ---- store P^T[u][i] into sW ----
    #pragma unroll
    for (int c = 0; c < 8; c++) {
        *(float4*)&sW[(j0 + c) * STR + i0] =
            make_float4(p[0][c], p[1][c], p[2][c], p[3][c]);
    }

    // ---- G3: U[u][d] = sum_f X^T[f][u] * N[f][d] ----
    gemm4x8(sX, sV, i0, j0, acc);      // rows = u, cols = d
    __syncthreads();                   // G3 reads of sV done + P^T visible
    #pragma unroll
    for (int r = 0; r < 4; r++) {
        float v0, v1, v2, v3, v4, v5, v6, v7;
        upk(acc[r * 4 + 0], v0, v1);
        upk(acc[r * 4 + 1], v2, v3);
        upk(acc[r * 4 + 2], v4, v5);
        upk(acc[r * 4 + 3], v6, v7);
        *(float4*)&sV[(i0 + r) * STR + j0] = make_float4(v0, v1, v2, v3);
        *(float4*)&sV[(i0 + r) * STR + j0 + 4] = make_float4(v4, v5, v6, v7);
    }
    __syncthreads();

    // ---- G4: H[i][d] = sum_u P^T[u][i] * U[u][d] ----
    gemm4x8(sW, sV, i0, j0, acc);      // rows = i, cols = d

    // ---- LayerNorm + exact GELU + store ----
    float4 g0 = *(const float4*)(gamma + j0);
    float4 g1 = *(const float4*)(gamma + j0 + 4);
    float4 b0 = *(const float4*)(beta + j0);
    float4 b1 = *(const float4*)(beta + j0 + 4);
    float gc[8] = {g0.x, g0.y, g0.z, g0.w, g1.x, g1.y, g1.z, g1.w};
    float bc[8] = {b0.x, b0.y, b0.z, b0.w, b1.x, b1.y, b1.z, b1.w};

    float* outp = out + ((size_t)b * 2 * SEQ + n * WIN) * D;
    #pragma unroll
    for (int r = 0; r < 4; r++) {
        float v[8];
        upk(acc[r * 4 + 0], v[0], v[1]);
        upk(acc[r * 4 + 1], v[2], v[3]);
        upk(acc[r * 4 + 2], v[4], v[5]);
        upk(acc[r * 4 + 3], v[6], v[7]);
        float s = 0.f;
        #pragma unroll
        for (int c = 0; c < 8; c++) s += v[c];
        s = rsum16(s);
        float mu = s * (1.0f / 128.0f);
        float var = 0.f;
        #pragma unroll
        for (int c = 0; c < 8; c++) {
            float dlt = v[c] - mu;
            var += dlt * dlt;
        }
        var = rsum16(var);
        float rstd = rsqrtf(var * (1.0f / 128.0f) + 1e-5f);
        float o[8];
        #pragma unroll
        for (int c = 0; c < 8; c++)
            o[c] = gelu((v[c] - mu) * rstd * gc[c] + bc[c]);
        *(float4*)&outp[(i0 + r) * D + j0] = make_float4(o[0], o[1], o[2], o[3]);
        *(float4*)&outp[(i0 + r) * D + j0 + 4] =
            make_float4(o[4], o[5], o[6], o[7]);
    }
}

// ---------------------------------------------------------------------------
extern "C" void kernel_launch(void* const* d_in, const int* in_sizes, int n_in,
                              void* d_out, int out_size) {
    const float* x     = (const float*)d_in[0];
    const float* Wq    = (const float*)d_in[1];
    const float* Wk    = (const float*)d_in[2];
    const float* Wv    = (const float*)d_in[3];
    const float* Wo    = (const float*)d_in[4];
    const float* gamma = (const float*)d_in[5];
    const float* beta  = (const float*)d_in[6];
    float* out = (float*)d_out;

    cudaFuncSetAttribute(attn_kernel,
                         cudaFuncAttributeMaxDynamicSharedMemorySize,
                         SMEM_BYTES);

    precompute_kernel<<<256, 128>>>(Wq, Wk, Wv, Wo);
    attn_kernel<<<BATCH * (SEQ / WIN), 512, SMEM_BYTES>>>(x, gamma, beta, out);
}

// round 6
// speedup vs baseline: 1.6234x; 1.6234x over previous
#include <cuda_runtime.h>
#include <math.h>

#define D 128
#define WIN 128
#define BATCH 8
#define SEQ 8192
#define STR 132                        // smem row stride in floats (k-major rows)
#define GB_OFF (3 * 128 * STR)         // gelu(beta) table after 3 buffers
#define SMEM_BYTES ((3 * 128 * STR + 128) * 4)
#define SCALE 0.08838834764831845f     // 1/sqrt(128)

typedef unsigned long long ull;

// Fused weights, row-major [d][j]:  g_M = (Wq Wk^T)*SCALE,  g_N = Wv Wo
__device__ float g_M[D * D];
__device__ float g_N[D * D];

// ---------------- f32x2 helpers ----------------
__device__ __forceinline__ ull pk(float x, float y) {
    ull r;
    asm("mov.b64 %0, {%1, %2};" : "=l"(r) : "f"(x), "f"(y));
    return r;
}
__device__ __forceinline__ void upk(ull v, float& x, float& y) {
    asm("mov.b64 {%0, %1}, %2;" : "=f"(x), "=f"(y) : "l"(v));
}
__device__ __forceinline__ void fma2(ull& d, ull a, ull b) {
    asm("fma.rn.f32x2 %0, %1, %2, %0;" : "+l"(d) : "l"(a), "l"(b));
}
__device__ __forceinline__ float rmax16(float v) {
    #pragma unroll
    for (int off = 8; off; off >>= 1)
        v = fmaxf(v, __shfl_xor_sync(0xffffffffu, v, off, 16));
    return v;
}
__device__ __forceinline__ float rsum16(float v) {
    #pragma unroll
    for (int off = 8; off; off >>= 1)
        v += __shfl_xor_sync(0xffffffffu, v, off, 16);
    return v;
}
__device__ __forceinline__ float gelu(float y) {
    return 0.5f * y * (1.f + erff(y * 0.70710678118654752f));
}

// ---------------------------------------------------------------------------
// Precompute fused weights. grid=256: blocks 0..127 -> M row d, 128..255 -> N.
// ---------------------------------------------------------------------------
__global__ void __launch_bounds__(128, 8)
precompute_kernel(const float* __restrict__ Wq, const float* __restrict__ Wk,
                  const float* __restrict__ Wv, const float* __restrict__ Wo) {
    __shared__ float w[D];
    int t = threadIdx.x;
    if (blockIdx.x < 128) {
        int d = blockIdx.x;
        w[t] = Wq[d * D + t];
        __syncthreads();
        const float4* row = (const float4*)(Wk + t * D);
        float a0 = 0.f, a1 = 0.f, a2 = 0.f, a3 = 0.f;
        #pragma unroll
        for (int f4 = 0; f4 < 32; f4 += 4) {
            float4 k0 = __ldg(&row[f4 + 0]);
            float4 k1 = __ldg(&row[f4 + 1]);
            float4 k2 = __ldg(&row[f4 + 2]);
            float4 k3 = __ldg(&row[f4 + 3]);
            a0 += w[f4*4+0]*k0.x + w[f4*4+1]*k0.y + w[f4*4+2]*k0.z + w[f4*4+3]*k0.w;
            a1 += w[f4*4+4]*k1.x + w[f4*4+5]*k1.y + w[f4*4+6]*k1.z + w[f4*4+7]*k1.w;
            a2 += w[f4*4+8]*k2.x + w[f4*4+9]*k2.y + w[f4*4+10]*k2.z + w[f4*4+11]*k2.w;
            a3 += w[f4*4+12]*k3.x + w[f4*4+13]*k3.y + w[f4*4+14]*k3.z + w[f4*4+15]*k3.w;
        }
        g_M[d * D + t] = (a0 + a1 + a2 + a3) * SCALE;
    } else {
        int d = blockIdx.x - 128;
        w[t] = Wv[d * D + t];
        __syncthreads();
        float a0 = 0.f, a1 = 0.f, a2 = 0.f, a3 = 0.f;
        #pragma unroll 8
        for (int f = 0; f < D; f += 4) {
            a0 += w[f + 0] * __ldg(&Wo[(f + 0) * D + t]);
            a1 += w[f + 1] * __ldg(&Wo[(f + 1) * D + t]);
            a2 += w[f + 2] * __ldg(&Wo[(f + 2) * D + t]);
            a3 += w[f + 3] * __ldg(&Wo[(f + 3) * D + t]);
        }
        g_N[d * D + t] = a0 + a1 + a2 + a3;
    }
}

// ---------------------------------------------------------------------------
// 8x8 register-tile GEMM, row-paired f32x2 accumulators.
//   acc[rp*8+c] = (C[i0+2rp][j0+c], C[i0+2rp+1][j0+c])
//   a-pairs come straight out of LDS.128 (no packing); b values duplicated.
// ---------------------------------------------------------------------------
__device__ __forceinline__ void gemm8x8(const float* __restrict__ A,
                                        const float* __restrict__ B,
                                        int i0, int j0, ull acc[32]) {
    #pragma unroll
    for (int q = 0; q < 32; q++) acc[q] = 0ull;

    const float* ar = A + i0;
    const float* br = B + j0;
    #pragma unroll 4
    for (int k = 0; k < D; k++) {
        float4 a0 = *(const float4*)(ar);
        float4 a1 = *(const float4*)(ar + 4);
        float4 b0 = *(const float4*)(br);
        float4 b1 = *(const float4*)(br + 4);
        ar += STR; br += STR;
        ull ap[4];
        ap[0] = pk(a0.x, a0.y);  // rows i0+0, i0+1  (register-pair alias)
        ap[1] = pk(a0.z, a0.w);
        ap[2] = pk(a1.x, a1.y);
        ap[3] = pk(a1.z, a1.w);
        float bv[8] = {b0.x, b0.y, b0.z, b0.w, b1.x, b1.y, b1.z, b1.w};
        #pragma unroll
        for (int c = 0; c < 8; c++) {
            ull bd = pk(bv[c], bv[c]);
            fma2(acc[0 * 8 + c], ap[0], bd);
            fma2(acc[1 * 8 + c], ap[1], bd);
            fma2(acc[2 * 8 + c], ap[2], bd);
            fma2(acc[3 * 8 + c], ap[3], bd);
        }
    }
}

// Unpack row-paired acc into v[row][col]
__device__ __forceinline__ void unpack8x8(const ull acc[32], float v[8][8]) {
    #pragma unroll
    for (int rp = 0; rp < 4; rp++)
        #pragma unroll
        for (int c = 0; c < 8; c++)
            upk(acc[rp * 8 + c], v[2 * rp][c], v[2 * rp + 1][c]);
}

// Store v (rows i0.., cols j0..) into buf row-major stride STR
__device__ __forceinline__ void store8x8(float* buf, int i0, int j0,
                                         const float v[8][8]) {
    #pragma unroll
    for (int r = 0; r < 8; r++) {
        *(float4*)&buf[(i0 + r) * STR + j0] =
            make_float4(v[r][0], v[r][1], v[r][2], v[r][3]);
        *(float4*)&buf[(i0 + r) * STR + j0 + 4] =
            make_float4(v[r][4], v[r][5], v[r][6], v[r][7]);
    }
}

// ---------------------------------------------------------------------------
// Main fused kernel: one CTA per (batch, 128-token block). 256 threads.
// Thread (tx = tid&15, ty = tid>>4) owns rows i0 = ty*8, cols j0 = tx*8.
// Buffers (k-major [k][row], stride STR):
//   sX = X^T[d][i]      sW = M[d][j] -> T^T[j][i] -> P^T[u][i]
//   sV = N[d][j] -> U[u][d]
// Also writes the constant (zero-padded-input) half block: gelu(beta).
// ---------------------------------------------------------------------------
__global__ void __launch_bounds__(256, 1)
attn_kernel(const float* __restrict__ x, const float* __restrict__ gamma,
            const float* __restrict__ beta, float* __restrict__ out) {
    extern __shared__ float sm[];
    float* sX = sm;
    float* sW = sm + 128 * STR;
    float* sV = sm + 2 * 128 * STR;
    float* sGB = sm + GB_OFF;

    const int tid = threadIdx.x;
    const int tx = tid & 15, ty = tid >> 4;
    const int i0 = ty * 8, j0 = tx * 8;
    const int blk = blockIdx.x;
    const int b = blk >> 6, n = blk & 63;

    // ---- stage X^T, M, N; gelu(beta) table ----
    {
        const float4* Xg4 = (const float4*)(x + (b * SEQ + n * WIN) * D);
        const float4* M4 = (const float4*)g_M;
        const float4* N4 = (const float4*)g_N;
        #pragma unroll 4
        for (int i = tid; i < 4096; i += 256) {
            int r = i >> 5;            // row (token for X, k for W)
            int c4 = (i & 31) * 4;     // feature base
            float4 v = Xg4[i];
            sX[(c4 + 0) * STR + r] = v.x;
            sX[(c4 + 1) * STR + r] = v.y;
            sX[(c4 + 2) * STR + r] = v.z;
            sX[(c4 + 3) * STR + r] = v.w;
            *(float4*)&sW[r * STR + c4] = M4[i];
            *(float4*)&sV[r * STR + c4] = N4[i];
        }
        if (tid < 128) sGB[tid] = gelu(beta[tid]);
    }
    __syncthreads();

    // ---- constant half block: out[b][S + n*WIN ..] = gelu(beta) (overlaps G1) ----
    {
        float4* dst = (float4*)(out + ((size_t)b * 2 * SEQ + SEQ + n * WIN) * D);
        #pragma unroll
        for (int q = 0; q < 16; q++) {
            int idx = q * 256 + tid;       // coalesced float4 index
            int c = (idx & 31) * 4;
            dst[idx] = make_float4(sGB[c], sGB[c + 1], sGB[c + 2], sGB[c + 3]);
        }
    }

    ull acc[32];
    float v[8][8];

    // ---- G1: T^T[j][i] = sum_d M[d][j] * X^T[d][i]  (scale folded in M) ----
    gemm8x8(sW, sX, i0, j0, acc);      // rows = j, cols = i
    unpack8x8(acc, v);
    __syncthreads();                   // all G1 reads of sW done
    store8x8(sW, i0, j0, v);
    __syncthreads();

    // ---- G2: S[i][u] = sum_f T^T[f][i] * X^T[f][u] ----
    gemm8x8(sW, sX, i0, j0, acc);      // rows = i, cols = u
    unpack8x8(acc, v);

    // ---- softmax over u (across 16 tx lanes) ----
    #pragma unroll
    for (int r = 0; r < 8; r++) {
        float m = v[r][0];
        #pragma unroll
        for (int c = 1; c < 8; c++) m = fmaxf(m, v[r][c]);
        m = rmax16(m);
        float s = 0.f;
        #pragma unroll
        for (int c = 0; c < 8; c++) {
            v[r][c] = __expf(v[r][c] - m);
            s += v[r][c];
        }
        s = rsum16(s);
        float inv = 1.0f / s;
        #pragma unroll
        for (int c = 0; c < 8; c++) v[r][c] *= inv;
    }
    __syncthreads();                   // all G2 reads of sW done

    // ---- store P^T[u][i] into sW ----
    #pragma unroll
    for (int c = 0; c < 8; c++) {
        *(float4*)&sW[(j0 + c) * STR + i0] =
            make_float4(v[0][c], v[1][c], v[2][c], v[3][c]);
        *(float4*)&sW[(j0 + c) * STR + i0 + 4] =
            make_float4(v[4][c], v[5][c], v[6][c], v[7][c]);
    }

    // ---- G3: U[u][d] = sum_f X^T[f][u] * N[f][d] ----
    gemm8x8(sX, sV, i0, j0, acc);      // rows = u, cols = d
    unpack8x8(acc, v);
    __syncthreads();                   // G3 reads of sV done + P^T visible
    store8x8(sV, i0, j0, v);
    __syncthreads();

    // ---- G4: H[i][d] = sum_u P^T[u][i] * U[u][d] ----
    gemm8x8(sW, sV, i0, j0, acc);      // rows = i, cols = d
    unpack8x8(acc, v);

    // ---- LayerNorm + exact GELU + store ----
    float4 g0 = *(const float4*)(gamma + j0);
    float4 g1 = *(const float4*)(gamma + j0 + 4);
    float4 b0 = *(const float4*)(beta + j0);
    float4 b1 = *(const float4*)(beta + j0 + 4);
    float gc[8] = {g0.x, g0.y, g0.z, g0.w, g1.x, g1.y, g1.z, g1.w};
    float bc[8] = {b0.x, b0.y, b0.z, b0.w, b1.x, b1.y, b1.z, b1.w};

    float* outp = out + ((size_t)b * 2 * SEQ + n * WIN) * D;
    #pragma unroll
    for (int r = 0; r < 8; r++) {
        float s = 0.f;
        #pragma unroll
        for (int c = 0; c < 8; c++) s += v[r][c];
        s = rsum16(s);
        float mu = s * (1.0f / 128.0f);
        float var = 0.f;
        #pragma unroll
        for (int c = 0; c < 8; c++) {
            float dlt = v[r][c] - mu;
            var += dlt * dlt;
        }
        var = rsum16(var);
        float rstd = rsqrtf(var * (1.0f / 128.0f) + 1e-5f);
        float o[8];
        #pragma unroll
        for (int c = 0; c < 8; c++)
            o[c] = gelu((v[r][c] - mu) * rstd * gc[c] + bc[c]);
        *(float4*)&outp[(i0 + r) * D + j0] = make_float4(o[0], o[1], o[2], o[3]);
        *(float4*)&outp[(i0 + r) * D + j0 + 4] =
            make_float4(o[4], o[5], o[6], o[7]);
    }
}

// ---------------------------------------------------------------------------
extern "C" void kernel_launch(void* const* d_in, const int* in_sizes, int n_in,
                              void* d_out, int out_size) {
    const float* x     = (const float*)d_in[0];
    const float* Wq    = (const float*)d_in[1];
    const float* Wk    = (const float*)d_in[2];
    const float* Wv    = (const float*)d_in[3];
    const float* Wo    = (const float*)d_in[4];
    const float* gamma = (const float*)d_in[5];
    const float* beta  = (const float*)d_in[6];
    float* out = (float*)d_out;

    cudaFuncSetAttribute(attn_kernel,
                         cudaFuncAttributeMaxDynamicSharedMemorySize,
                         SMEM_BYTES);

    precompute_kernel<<<256, 128>>>(Wq, Wk, Wv, Wo);
    attn_kernel<<<BATCH * (SEQ / WIN), 256, SMEM_BYTES>>>(x, gamma, beta, out);
}

// round 7
// speedup vs baseline: 1.6512x; 1.0171x over previous
#include <cuda_runtime.h>
#include <math.h>

#define D 128
#define WIN 128
#define BATCH 8
#define SEQ 8192
#define STR 132                        // smem row stride in floats (k-major rows)
#define GB_OFF (3 * 128 * STR)         // gelu(beta) table after 3 buffers
#define SMEM_BYTES ((3 * 128 * STR + 128) * 4)
#define SCALE 0.08838834764831845f     // 1/sqrt(128)

typedef unsigned long long ull;

// Fused weights, row-major [d][j]:  g_M = (Wq Wk^T)*SCALE,  g_N = Wv Wo
__device__ float g_M[D * D];
__device__ float g_N[D * D];

// ---------------- f32x2 helpers ----------------
__device__ __forceinline__ ull pk(float x, float y) {
    ull r;
    asm("mov.b64 %0, {%1, %2};" : "=l"(r) : "f"(x), "f"(y));
    return r;
}
__device__ __forceinline__ void upk(ull v, float& x, float& y) {
    asm("mov.b64 {%0, %1}, %2;" : "=f"(x), "=f"(y) : "l"(v));
}
__device__ __forceinline__ void fma2(ull& d, ull a, ull b) {
    asm("fma.rn.f32x2 %0, %1, %2, %0;" : "+l"(d) : "l"(a), "l"(b));
}
__device__ __forceinline__ float rmax16(float v) {
    #pragma unroll
    for (int off = 8; off; off >>= 1)
        v = fmaxf(v, __shfl_xor_sync(0xffffffffu, v, off, 16));
    return v;
}
__device__ __forceinline__ float rsum16(float v) {
    #pragma unroll
    for (int off = 8; off; off >>= 1)
        v += __shfl_xor_sync(0xffffffffu, v, off, 16);
    return v;
}
__device__ __forceinline__ float gelu(float y) {
    return 0.5f * y * (1.f + erff(y * 0.70710678118654752f));
}

// ---------------------------------------------------------------------------
// Precompute fused weights. grid=256: blocks 0..127 -> M row d, 128..255 -> N.
// ---------------------------------------------------------------------------
__global__ void __launch_bounds__(128, 8)
precompute_kernel(const float* __restrict__ Wq, const float* __restrict__ Wk,
                  const float* __restrict__ Wv, const float* __restrict__ Wo) {
    __shared__ float w[D];
    int t = threadIdx.x;
    if (blockIdx.x < 128) {
        int d = blockIdx.x;
        w[t] = Wq[d * D + t];
        __syncthreads();
        const float4* row = (const float4*)(Wk + t * D);
        float a0 = 0.f, a1 = 0.f, a2 = 0.f, a3 = 0.f;
        #pragma unroll
        for (int f4 = 0; f4 < 32; f4 += 4) {
            float4 k0 = __ldg(&row[f4 + 0]);
            float4 k1 = __ldg(&row[f4 + 1]);
            float4 k2 = __ldg(&row[f4 + 2]);
            float4 k3 = __ldg(&row[f4 + 3]);
            a0 += w[f4*4+0]*k0.x + w[f4*4+1]*k0.y + w[f4*4+2]*k0.z + w[f4*4+3]*k0.w;
            a1 += w[f4*4+4]*k1.x + w[f4*4+5]*k1.y + w[f4*4+6]*k1.z + w[f4*4+7]*k1.w;
            a2 += w[f4*4+8]*k2.x + w[f4*4+9]*k2.y + w[f4*4+10]*k2.z + w[f4*4+11]*k2.w;
            a3 += w[f4*4+12]*k3.x + w[f4*4+13]*k3.y + w[f4*4+14]*k3.z + w[f4*4+15]*k3.w;
        }
        g_M[d * D + t] = (a0 + a1 + a2 + a3) * SCALE;
    } else {
        int d = blockIdx.x - 128;
        w[t] = Wv[d * D + t];
        __syncthreads();
        float a0 = 0.f, a1 = 0.f, a2 = 0.f, a3 = 0.f;
        #pragma unroll 8
        for (int f = 0; f < D; f += 4) {
            a0 += w[f + 0] * __ldg(&Wo[(f + 0) * D + t]);
            a1 += w[f + 1] * __ldg(&Wo[(f + 1) * D + t]);
            a2 += w[f + 2] * __ldg(&Wo[(f + 2) * D + t]);
            a3 += w[f + 3] * __ldg(&Wo[(f + 3) * D + t]);
        }
        g_N[d * D + t] = a0 + a1 + a2 + a3;
    }
}

// ---------------------------------------------------------------------------
// 8x8 register-tile GEMM, row-paired f32x2 accumulators, software-pipelined:
// loads for iteration k+1 are issued BEFORE the FMAs of iteration k, so each
// warp hides the 29-cyc LDS latency under its own 32 fma2 (~64+ SMSP cycles).
//   acc[rp*8+c] = (C[i0+2rp][j0+c], C[i0+2rp+1][j0+c])
// ---------------------------------------------------------------------------
__device__ __forceinline__ void fma_step(const float4& a0, const float4& a1,
                                         const float4& b0, const float4& b1,
                                         ull acc[32]) {
    ull ap[4];
    ap[0] = pk(a0.x, a0.y);
    ap[1] = pk(a0.z, a0.w);
    ap[2] = pk(a1.x, a1.y);
    ap[3] = pk(a1.z, a1.w);
    float bv[8] = {b0.x, b0.y, b0.z, b0.w, b1.x, b1.y, b1.z, b1.w};
    #pragma unroll
    for (int c = 0; c < 8; c++) {
        ull bd = pk(bv[c], bv[c]);
        fma2(acc[0 * 8 + c], ap[0], bd);
        fma2(acc[1 * 8 + c], ap[1], bd);
        fma2(acc[2 * 8 + c], ap[2], bd);
        fma2(acc[3 * 8 + c], ap[3], bd);
    }
}

__device__ __forceinline__ void gemm8x8(const float* __restrict__ A,
                                        const float* __restrict__ B,
                                        int i0, int j0, ull acc[32]) {
    #pragma unroll
    for (int q = 0; q < 32; q++) acc[q] = 0ull;

    const float* ar = A + i0;
    const float* br = B + j0;
    float4 a0 = *(const float4*)(ar);
    float4 a1 = *(const float4*)(ar + 4);
    float4 b0 = *(const float4*)(br);
    float4 b1 = *(const float4*)(br + 4);
    #pragma unroll 4
    for (int k = 0; k < D - 1; k++) {
        ar += STR; br += STR;
        float4 na0 = *(const float4*)(ar);
        float4 na1 = *(const float4*)(ar + 4);
        float4 nb0 = *(const float4*)(br);
        float4 nb1 = *(const float4*)(br + 4);
        fma_step(a0, a1, b0, b1, acc);
        a0 = na0; a1 = na1; b0 = nb0; b1 = nb1;
    }
    fma_step(a0, a1, b0, b1, acc);
}

// Unpack row-paired acc into v[row][col]
__device__ __forceinline__ void unpack8x8(const ull acc[32], float v[8][8]) {
    #pragma unroll
    for (int rp = 0; rp < 4; rp++)
        #pragma unroll
        for (int c = 0; c < 8; c++)
            upk(acc[rp * 8 + c], v[2 * rp][c], v[2 * rp + 1][c]);
}

// Store v (rows i0.., cols j0..) into buf row-major stride STR
__device__ __forceinline__ void store8x8(float* buf, int i0, int j0,
                                         const float v[8][8]) {
    #pragma unroll
    for (int r = 0; r < 8; r++) {
        *(float4*)&buf[(i0 + r) * STR + j0] =
            make_float4(v[r][0], v[r][1], v[r][2], v[r][3]);
        *(float4*)&buf[(i0 + r) * STR + j0 + 4] =
            make_float4(v[r][4], v[r][5], v[r][6], v[r][7]);
    }
}

// ---------------------------------------------------------------------------
// Main fused kernel: one CTA per (batch, 128-token block). 256 threads.
// Thread (tx = tid&15, ty = tid>>4) owns rows i0 = ty*8, cols j0 = tx*8.
// Buffers (k-major [k][row], stride STR):
//   sX = X^T[d][i]      sW = M[d][j] -> T^T[j][i] -> P^T[u][i]
//   sV = N[d][j] -> U[u][d]
// Also writes the constant (zero-padded-input) half block: gelu(beta).
// ---------------------------------------------------------------------------
__global__ void __launch_bounds__(256, 1)
attn_kernel(const float* __restrict__ x, const float* __restrict__ gamma,
            const float* __restrict__ beta, float* __restrict__ out) {
    extern __shared__ float sm[];
    float* sX = sm;
    float* sW = sm + 128 * STR;
    float* sV = sm + 2 * 128 * STR;
    float* sGB = sm + GB_OFF;

    const int tid = threadIdx.x;
    const int tx = tid & 15, ty = tid >> 4;
    const int i0 = ty * 8, j0 = tx * 8;
    const int blk = blockIdx.x;
    const int b = blk >> 6, n = blk & 63;

    // ---- stage X^T, M, N; gelu(beta) table ----
    {
        const float4* Xg4 = (const float4*)(x + (b * SEQ + n * WIN) * D);
        const float4* M4 = (const float4*)g_M;
        const float4* N4 = (const float4*)g_N;
        #pragma unroll 4
        for (int i = tid; i < 4096; i += 256) {
            int r = i >> 5;            // row (token for X, k for W)
            int c4 = (i & 31) * 4;     // feature base
            float4 v = Xg4[i];
            sX[(c4 + 0) * STR + r] = v.x;
            sX[(c4 + 1) * STR + r] = v.y;
            sX[(c4 + 2) * STR + r] = v.z;
            sX[(c4 + 3) * STR + r] = v.w;
            *(float4*)&sW[r * STR + c4] = M4[i];
            *(float4*)&sV[r * STR + c4] = N4[i];
        }
        if (tid < 128) sGB[tid] = gelu(beta[tid]);
    }
    __syncthreads();

    // ---- constant half block: out[b][S + n*WIN ..] = gelu(beta) (overlaps G1) ----
    {
        float4* dst = (float4*)(out + ((size_t)b * 2 * SEQ + SEQ + n * WIN) * D);
        #pragma unroll
        for (int q = 0; q < 16; q++) {
            int idx = q * 256 + tid;       // coalesced float4 index
            int c = (idx & 31) * 4;
            dst[idx] = make_float4(sGB[c], sGB[c + 1], sGB[c + 2], sGB[c + 3]);
        }
    }

    ull acc[32];
    float v[8][8];

    // ---- G1: T^T[j][i] = sum_d M[d][j] * X^T[d][i]  (scale folded in M) ----
    gemm8x8(sW, sX, i0, j0, acc);      // rows = j, cols = i
    unpack8x8(acc, v);
    __syncthreads();                   // all G1 reads of sW done
    store8x8(sW, i0, j0, v);
    __syncthreads();

    // ---- G2: S[i][u] = sum_f T^T[f][i] * X^T[f][u] ----
    gemm8x8(sW, sX, i0, j0, acc);      // rows = i, cols = u
    unpack8x8(acc, v);

    // ---- softmax over u (across 16 tx lanes) ----
    #pragma unroll
    for (int r = 0; r < 8; r++) {
        float m = v[r][0];
        #pragma unroll
        for (int c = 1; c < 8; c++) m = fmaxf(m, v[r][c]);
        m = rmax16(m);
        float s = 0.f;
        #pragma unroll
        for (int c = 0; c < 8; c++) {
            v[r][c] = __expf(v[r][c] - m);
            s += v[r][c];
        }
        s = rsum16(s);
        float inv = 1.0f / s;
        #pragma unroll
        for (int c = 0; c < 8; c++) v[r][c] *= inv;
    }
    __syncthreads();                   // all G2 reads of sW done

    // ---- store P^T[u][i] into sW ----
    #pragma unroll
    for (int c = 0; c < 8; c++) {
        *(float4*)&sW[(j0 + c) * STR + i0] =
            make_float4(v[0][c], v[1][c], v[2][c], v[3][c]);
        *(float4*)&sW[(j0 + c) * STR + i0 + 4] =
            make_float4(v[4][c], v[5][c], v[6][c], v[7][c]);
    }

    // ---- G3: U[u][d] = sum_f X^T[f][u] * N[f][d] ----
    gemm8x8(sX, sV, i0, j0, acc);      // rows = u, cols = d
    unpack8x8(acc, v);
    __syncthreads();                   // G3 reads of sV done + P^T visible
    store8x8(sV, i0, j0, v);
    __syncthreads();

    // ---- G4: H[i][d] = sum_u P^T[u][i] * U[u][d] ----
    gemm8x8(sW, sV, i0, j0, acc);      // rows = i, cols = d
    unpack8x8(acc, v);

    // ---- LayerNorm + exact GELU + store ----
    float4 g0 = *(const float4*)(gamma + j0);
    float4 g1 = *(const float4*)(gamma + j0 + 4);
    float4 b0 = *(const float4*)(beta + j0);
    float4 b1 = *(const float4*)(beta + j0 + 4);
    float gc[8] = {g0.x, g0.y, g0.z, g0.w, g1.x, g1.y, g1.z, g1.w};
    float bc[8] = {b0.x, b0.y, b0.z, b0.w, b1.x, b1.y, b1.z, b1.w};

    float* outp = out + ((size_t)b * 2 * SEQ + n * WIN) * D;
    #pragma unroll
    for (int r = 0; r < 8; r++) {
        float s = 0.f;
        #pragma unroll
        for (int c = 0; c < 8; c++) s += v[r][c];
        s = rsum16(s);
        float mu = s * (1.0f / 128.0f);
        float var = 0.f;
        #pragma unroll
        for (int c = 0; c < 8; c++) {
            float dlt = v[r][c] - mu;
            var += dlt * dlt;
        }
        var = rsum16(var);
        float rstd = rsqrtf(var * (1.0f / 128.0f) + 1e-5f);
        float o[8];
        #pragma unroll
        for (int c = 0; c < 8; c++)
            o[c] = gelu((v[r][c] - mu) * rstd * gc[c] + bc[c]);
        *(float4*)&outp[(i0 + r) * D + j0] = make_float4(o[0], o[1], o[2], o[3]);
        *(float4*)&outp[(i0 + r) * D + j0 + 4] =
            make_float4(o[4], o[5], o[6], o[7]);
    }
}

// ---------------------------------------------------------------------------
extern "C" void kernel_launch(void* const* d_in, const int* in_sizes, int n_in,
                              void* d_out, int out_size) {
    const float* x     = (const float*)d_in[0];
    const float* Wq    = (const float*)d_in[1];
    const float* Wk    = (const float*)d_in[2];
    const float* Wv    = (const float*)d_in[3];
    const float* Wo    = (const float*)d_in[4];
    const float* gamma = (const float*)d_in[5];
    const float* beta  = (const float*)d_in[6];
    float* out = (float*)d_out;

    cudaFuncSetAttribute(attn_kernel,
                         cudaFuncAttributeMaxDynamicSharedMemorySize,
                         SMEM_BYTES);

    precompute_kernel<<<256, 128>>>(Wq, Wk, Wv, Wo);
    attn_kernel<<<BATCH * (SEQ / WIN), 256, SMEM_BYTES>>>(x, gamma, beta, out);
}

// round 8
// speedup vs baseline: 1.7564x; 1.0637x over previous
#include <cuda_runtime.h>
#include <math.h>

#define D 128
#define WIN 128
#define BATCH 8
#define SEQ 8192
#define STR 132                        // smem row stride in floats (k-major rows)
#define GB_OFF (3 * 128 * STR)         // gelu(beta) table after 3 buffers
#define SMEM_BYTES ((3 * 128 * STR + 128 + 512) * 4)
#define SCALE 0.08838834764831845f     // 1/sqrt(128)

typedef unsigned long long ull;

// Fused weights, row-major [d][j]:  g_M = (Wq Wk^T)*SCALE,  g_N = Wv Wo
__device__ float g_M[D * D];
__device__ float g_N[D * D];

// ---------------- f32x2 helpers ----------------
__device__ __forceinline__ ull pk(float x, float y) {
    ull r;
    asm("mov.b64 %0, {%1, %2};" : "=l"(r) : "f"(x), "f"(y));
    return r;
}
__device__ __forceinline__ void upk(ull v, float& x, float& y) {
    asm("mov.b64 {%0, %1}, %2;" : "=f"(x), "=f"(y) : "l"(v));
}
__device__ __forceinline__ void fma2(ull& d, ull a, ull b) {
    asm("fma.rn.f32x2 %0, %1, %2, %0;" : "+l"(d) : "l"(a), "l"(b));
}
__device__ __forceinline__ float gelu(float y) {
    return 0.5f * y * (1.f + erff(y * 0.70710678118654752f));
}

// ---------------------------------------------------------------------------
// Precompute fused weights. grid=256: blocks 0..127 -> M row d, 128..255 -> N.
// ---------------------------------------------------------------------------
__global__ void __launch_bounds__(128, 8)
precompute_kernel(const float* __restrict__ Wq, const float* __restrict__ Wk,
                  const float* __restrict__ Wv, const float* __restrict__ Wo) {
    __shared__ float w[D];
    int t = threadIdx.x;
    if (blockIdx.x < 128) {
        int d = blockIdx.x;
        w[t] = Wq[d * D + t];
        __syncthreads();
        const float4* row = (const float4*)(Wk + t * D);
        float a0 = 0.f, a1 = 0.f, a2 = 0.f, a3 = 0.f;
        #pragma unroll
        for (int f4 = 0; f4 < 32; f4 += 4) {
            float4 k0 = __ldg(&row[f4 + 0]);
            float4 k1 = __ldg(&row[f4 + 1]);
            float4 k2 = __ldg(&row[f4 + 2]);
            float4 k3 = __ldg(&row[f4 + 3]);
            a0 += w[f4*4+0]*k0.x + w[f4*4+1]*k0.y + w[f4*4+2]*k0.z + w[f4*4+3]*k0.w;
            a1 += w[f4*4+4]*k1.x + w[f4*4+5]*k1.y + w[f4*4+6]*k1.z + w[f4*4+7]*k1.w;
            a2 += w[f4*4+8]*k2.x + w[f4*4+9]*k2.y + w[f4*4+10]*k2.z + w[f4*4+11]*k2.w;
            a3 += w[f4*4+12]*k3.x + w[f4*4+13]*k3.y + w[f4*4+14]*k3.z + w[f4*4+15]*k3.w;
        }
        g_M[d * D + t] = (a0 + a1 + a2 + a3) * SCALE;
    } else {
        int d = blockIdx.x - 128;
        w[t] = Wv[d * D + t];
        __syncthreads();
        float a0 = 0.f, a1 = 0.f, a2 = 0.f, a3 = 0.f;
        #pragma unroll 8
        for (int f = 0; f < D; f += 4) {
            a0 += w[f + 0] * __ldg(&Wo[(f + 0) * D + t]);
            a1 += w[f + 1] * __ldg(&Wo[(f + 1) * D + t]);
            a2 += w[f + 2] * __ldg(&Wo[(f + 2) * D + t]);
            a3 += w[f + 3] * __ldg(&Wo[(f + 3) * D + t]);
        }
        g_N[d * D + t] = a0 + a1 + a2 + a3;
    }
}

// ---------------------------------------------------------------------------
// 8x8 register-tile GEMM, row-paired f32x2 accumulators.
//   Thread tile: rows i0..i0+7, cols {cA..cA+3, cB..cB+3}.
//   Every LDS.128's 8 distinct lane addresses pack one 128B window:
//     a: lanes lr 0..3 at 32B stride (rows), b: lanes lc 0..7 at 16B stride.
//   acc[rp*8+c] = (C[i0+2rp][col(c)], C[i0+2rp+1][col(c)]),
//     col(c) = cA + c for c<4, cB + c-4 for c>=4.
// ---------------------------------------------------------------------------
__device__ __forceinline__ void gemm8x8(const float* __restrict__ A,
                                        const float* __restrict__ B,
                                        int i0, int cA, int cB, ull acc[32]) {
    #pragma unroll
    for (int q = 0; q < 32; q++) acc[q] = 0ull;

    const float* ar = A + i0;
    const float* ba = B + cA;
    const float* bb = B + cB;
    #pragma unroll 4
    for (int k = 0; k < D; k++) {
        float4 a0 = *(const float4*)(ar);
        float4 a1 = *(const float4*)(ar + 4);
        float4 b0 = *(const float4*)(ba);
        float4 b1 = *(const float4*)(bb);
        ar += STR; ba += STR; bb += STR;
        ull ap[4];
        ap[0] = pk(a0.x, a0.y);
        ap[1] = pk(a0.z, a0.w);
        ap[2] = pk(a1.x, a1.y);
        ap[3] = pk(a1.z, a1.w);
        float bv[8] = {b0.x, b0.y, b0.z, b0.w, b1.x, b1.y, b1.z, b1.w};
        #pragma unroll
        for (int c = 0; c < 8; c++) {
            ull bd = pk(bv[c], bv[c]);
            fma2(acc[0 * 8 + c], ap[0], bd);
            fma2(acc[1 * 8 + c], ap[1], bd);
            fma2(acc[2 * 8 + c], ap[2], bd);
            fma2(acc[3 * 8 + c], ap[3], bd);
        }
    }
}

// Unpack row-paired acc into v[row][col]
__device__ __forceinline__ void unpack8x8(const ull acc[32], float v[8][8]) {
    #pragma unroll
    for (int rp = 0; rp < 4; rp++)
        #pragma unroll
        for (int c = 0; c < 8; c++)
            upk(acc[rp * 8 + c], v[2 * rp][c], v[2 * rp + 1][c]);
}

// Store v into buf (row-major stride STR) at rows i0.., col chunks cA/cB
__device__ __forceinline__ void store8x8(float* buf, int i0, int cA, int cB,
                                         const float v[8][8]) {
    #pragma unroll
    for (int r = 0; r < 8; r++) {
        *(float4*)&buf[(i0 + r) * STR + cA] =
            make_float4(v[r][0], v[r][1], v[r][2], v[r][3]);
        *(float4*)&buf[(i0 + r) * STR + cB] =
            make_float4(v[r][4], v[r][5], v[r][6], v[r][7]);
    }
}

// ---------------------------------------------------------------------------
// Main fused kernel: one CTA per (batch, 128-token block). 256 threads.
// Warp grid 4(rows) x 2(cols): warp wr covers rows wr*32..+31, wc cols wc*64..
// Lane: lr = l>>3 -> rows i0 = wr*32+lr*8; lc = l&7 -> cols cA = wc*64+lc*4,
// cB = cA+32. Row reductions: width-8 shfl + cross-warp-pair via smem.
// ---------------------------------------------------------------------------
__global__ void __launch_bounds__(256, 1)
attn_kernel(const float* __restrict__ x, const float* __restrict__ gamma,
            const float* __restrict__ beta, float* __restrict__ out) {
    extern __shared__ float sm[];
    float* sX = sm;
    float* sW = sm + 128 * STR;
    float* sV = sm + 2 * 128 * STR;
    float* sGB = sm + GB_OFF;
    float* redM = sGB + 128;           // [2][128]
    float* redS = redM + 256;          // [2][128]

    const int tid = threadIdx.x;
    const int wid = tid >> 5;
    const int wr = wid & 3, wc = wid >> 2;
    const int l = tid & 31;
    const int lr = l >> 3, lc = l & 7;
    const int i0 = wr * 32 + lr * 8;
    const int cA = wc * 64 + lc * 4, cB = cA + 32;
    const int blk = blockIdx.x;
    const int b = blk >> 6, n = blk & 63;

    // ---- stage X^T, M, N; gelu(beta) table ----
    {
        const float4* Xg4 = (const float4*)(x + (b * SEQ + n * WIN) * D);
        const float4* M4 = (const float4*)g_M;
        const float4* N4 = (const float4*)g_N;
        #pragma unroll 4
        for (int i = tid; i < 4096; i += 256) {
            int r = i >> 5;            // row (token for X, k for W)
            int c4 = (i & 31) * 4;     // feature base
            float4 v = Xg4[i];
            sX[(c4 + 0) * STR + r] = v.x;
            sX[(c4 + 1) * STR + r] = v.y;
            sX[(c4 + 2) * STR + r] = v.z;
            sX[(c4 + 3) * STR + r] = v.w;
            *(float4*)&sW[r * STR + c4] = M4[i];
            *(float4*)&sV[r * STR + c4] = N4[i];
        }
        if (tid < 128) sGB[tid] = gelu(beta[tid]);
    }
    __syncthreads();

    // ---- constant half block: out[b][S + n*WIN ..] = gelu(beta) ----
    {
        float4* dst = (float4*)(out + ((size_t)b * 2 * SEQ + SEQ + n * WIN) * D);
        #pragma unroll
        for (int q = 0; q < 16; q++) {
            int idx = q * 256 + tid;       // coalesced float4 index
            int c = (idx & 31) * 4;
            dst[idx] = make_float4(sGB[c], sGB[c + 1], sGB[c + 2], sGB[c + 3]);
        }
    }

    ull acc[32];
    float v[8][8];

    // ---- G1: T^T[j][i] = sum_d M[d][j] * X^T[d][i]  (scale folded in M) ----
    gemm8x8(sW, sX, i0, cA, cB, acc);  // rows = j, cols = i
    unpack8x8(acc, v);
    __syncthreads();                   // all G1 reads of sW done
    store8x8(sW, i0, cA, cB, v);
    __syncthreads();

    // ---- G2: S[i][u] = sum_f T^T[f][i] * X^T[f][u] ----
    gemm8x8(sW, sX, i0, cA, cB, acc);  // rows = i, cols = u
    unpack8x8(acc, v);

    // ---- softmax over u: width-8 shfl + warp-pair combine via smem ----
    {
        float gm[8];
        #pragma unroll
        for (int r = 0; r < 8; r++) {
            float m = v[r][0];
            #pragma unroll
            for (int c = 1; c < 8; c++) m = fmaxf(m, v[r][c]);
            #pragma unroll
            for (int off = 4; off; off >>= 1)
                m = fmaxf(m, __shfl_xor_sync(0xffffffffu, m, off, 8));
            gm[r] = m;
        }
        if (lc == 0) {
            #pragma unroll
            for (int r = 0; r < 8; r++) redM[wc * 128 + i0 + r] = gm[r];
        }
        __syncthreads();               // also: all threads past G2 reads of sW
        float gs[8];
        #pragma unroll
        for (int r = 0; r < 8; r++) {
            float m = fmaxf(redM[i0 + r], redM[128 + i0 + r]);
            float s = 0.f;
            #pragma unroll
            for (int c = 0; c < 8; c++) {
                v[r][c] = __expf(v[r][c] - m);
                s += v[r][c];
            }
            #pragma unroll
            for (int off = 4; off; off >>= 1)
                s += __shfl_xor_sync(0xffffffffu, s, off, 8);
            gs[r] = s;
        }
        if (lc == 0) {
            #pragma unroll
            for (int r = 0; r < 8; r++) redS[wc * 128 + i0 + r] = gs[r];
        }
        __syncthreads();
        #pragma unroll
        for (int r = 0; r < 8; r++) {
            float inv = 1.0f / (redS[i0 + r] + redS[128 + i0 + r]);
            #pragma unroll
            for (int c = 0; c < 8; c++) v[r][c] *= inv;
        }
    }

    // ---- store P^T[u][i] into sW (sW reads all done at softmax barrier) ----
    #pragma unroll
    for (int c = 0; c < 4; c++) {
        *(float4*)&sW[(cA + c) * STR + i0] =
            make_float4(v[0][c], v[1][c], v[2][c], v[3][c]);
        *(float4*)&sW[(cA + c) * STR + i0 + 4] =
            make_float4(v[4][c], v[5][c], v[6][c], v[7][c]);
    }
    #pragma unroll
    for (int c = 4; c < 8; c++) {
        *(float4*)&sW[(cB + c - 4) * STR + i0] =
            make_float4(v[0][c], v[1][c], v[2][c], v[3][c]);
        *(float4*)&sW[(cB + c - 4) * STR + i0 + 4] =
            make_float4(v[4][c], v[5][c], v[6][c], v[7][c]);
    }

    // ---- G3: U[u][d] = sum_f X^T[f][u] * N[f][d]  (doesn't touch sW) ----
    gemm8x8(sX, sV, i0, cA, cB, acc);  // rows = u, cols = d
    unpack8x8(acc, v);
    __syncthreads();                   // G3 reads of sV done; P^T visible
    store8x8(sV, i0, cA, cB, v);
    __syncthreads();

    // ---- G4: H[i][d] = sum_u P^T[u][i] * U[u][d] ----
    gemm8x8(sW, sV, i0, cA, cB, acc);  // rows = i, cols = d
    unpack8x8(acc, v);

    // ---- LayerNorm + exact GELU + store ----
    {
        float gs[8];
        #pragma unroll
        for (int r = 0; r < 8; r++) {
            float s = 0.f;
            #pragma unroll
            for (int c = 0; c < 8; c++) s += v[r][c];
            #pragma unroll
            for (int off = 4; off; off >>= 1)
                s += __shfl_xor_sync(0xffffffffu, s, off, 8);
            gs[r] = s;
        }
        if (lc == 0) {
            #pragma unroll
            for (int r = 0; r < 8; r++) redM[wc * 128 + i0 + r] = gs[r];
        }
        __syncthreads();
        float gv[8], mu[8];
        #pragma unroll
        for (int r = 0; r < 8; r++) {
            mu[r] = (redM[i0 + r] + redM[128 + i0 + r]) * (1.0f / 128.0f);
            float var = 0.f;
            #pragma unroll
            for (int c = 0; c < 8; c++) {
                float dlt = v[r][c] - mu[r];
                var += dlt * dlt;
            }
            #pragma unroll
            for (int off = 4; off; off >>= 1)
                var += __shfl_xor_sync(0xffffffffu, var, off, 8);
            gv[r] = var;
        }
        if (lc == 0) {
            #pragma unroll
            for (int r = 0; r < 8; r++) redS[wc * 128 + i0 + r] = gv[r];
        }
        __syncthreads();

        float4 ga = *(const float4*)(gamma + cA);
        float4 gb2 = *(const float4*)(gamma + cB);
        float4 ba = *(const float4*)(beta + cA);
        float4 bb = *(const float4*)(beta + cB);
        float gc[8] = {ga.x, ga.y, ga.z, ga.w, gb2.x, gb2.y, gb2.z, gb2.w};
        float bc[8] = {ba.x, ba.y, ba.z, ba.w, bb.x, bb.y, bb.z, bb.w};

        float* outp = out + ((size_t)b * 2 * SEQ + n * WIN) * D;
        #pragma unroll
        for (int r = 0; r < 8; r++) {
            float var = redS[i0 + r] + redS[128 + i0 + r];
            float rstd = rsqrtf(var * (1.0f / 128.0f) + 1e-5f);
            float o[8];
            #pragma unroll
            for (int c = 0; c < 8; c++)
                o[c] = gelu((v[r][c] - mu[r]) * rstd * gc[c] + bc[c]);
            *(float4*)&outp[(i0 + r) * D + cA] =
                make_float4(o[0], o[1], o[2], o[3]);
            *(float4*)&outp[(i0 + r) * D + cB] =
                make_float4(o[4], o[5], o[6], o[7]);
        }
    }
}

// ---------------------------------------------------------------------------
extern "C" void kernel_launch(void* const* d_in, const int* in_sizes, int n_in,
                              void* d_out, int out_size) {
    const float* x     = (const float*)d_in[0];
    const float* Wq    = (const float*)d_in[1];
    const float* Wk    = (const float*)d_in[2];
    const float* Wv    = (const float*)d_in[3];
    const float* Wo    = (const float*)d_in[4];
    const float* gamma = (const float*)d_in[5];
    const float* beta  = (const float*)d_in[6];
    float* out = (float*)d_out;

    cudaFuncSetAttribute(attn_kernel,
                         cudaFuncAttributeMaxDynamicSharedMemorySize,
                         SMEM_BYTES);

    precompute_kernel<<<256, 128>>>(Wq, Wk, Wv, Wo);
    attn_kernel<<<BATCH * (SEQ / WIN), 256, SMEM_BYTES>>>(x, gamma, beta, out);
}